// round 16
// baseline (speedup 1.0000x reference)
#include <cuda_runtime.h>
#include <cstdint>

#define SLATE   5
#define DDIM    20
#define KSEL    100
#define NBINS   2048
#define CAP     131072
#define SMAX    131072
#define SH_CAND 12288
#define SV_CAP  512
#define STGT    128        // sample-count guarantee target (>= KSEL)
#define RCHUNK  16         // refineA chunks per row

// -------- device scratch (allocation-free module globals) --------
__device__ float              g_h1[512];
__device__ float              g_proto[128];
__device__ unsigned           g_hist[SLATE * NBINS];
__device__ unsigned           g_hist2[SLATE * NBINS];
__device__ unsigned           g_skey[(size_t)SLATE * SMAX];   // sample keys
__device__ unsigned           g_coarseBA[8];                  // per-row coarse bin
__device__ unsigned           g_coarsePF[8];                  // prefix before bin
__device__ unsigned           g_thresh[8];                    // exclusive key limit
__device__ unsigned           g_candCount[8];
__device__ unsigned long long g_cand[(size_t)SLATE * CAP];
__device__ unsigned           g_done;                         // sample ticket
__device__ unsigned           g_rdone[8];                     // per-row refine tickets

__device__ __forceinline__ float leaky(float x) { return x > 0.0f ? x : 0.01f * x; }

// ---- scalar math: sample AND score use identical sequences (bit-identical keys)
__device__ __forceinline__ void unpack20(const float4* d5, float* vv) {
    #pragma unroll
    for (int q = 0; q < 5; q++) {
        float4 v = d5[q];
        vv[4*q+0] = v.x; vv[4*q+1] = v.y; vv[4*q+2] = v.z; vv[4*q+3] = v.w;
    }
}
__device__ __forceinline__ float norm20(const float* vv) {
    float c = 0.0f;
    #pragma unroll
    for (int k = 0; k < DDIM; k++) c = fmaf(vv[k], vv[k], c);
    return c;
}
__device__ __forceinline__ float dot20v(const float4* p, const float* vv) {
    float d = 0.0f;
    #pragma unroll
    for (int q = 0; q < 5; q++) {
        float4 w = p[q];
        d = fmaf(w.x, vv[4*q+0], d); d = fmaf(w.y, vv[4*q+1], d);
        d = fmaf(w.z, vv[4*q+2], d); d = fmaf(w.w, vv[4*q+3], d);
    }
    return d;
}
__device__ __forceinline__ unsigned key20(float cn2, float dot, float pn) {
    float d2 = fmaf(-2.0f, dot, cn2) + pn;
    d2 = fmaxf(d2, 0.0f);               // positive floats: raw bits monotone
    return __float_as_uint(d2);
}
// spn from shared proto — IDENTICAL fmaf order in sample and score => same bits
__device__ __forceinline__ float pn20(const float* sp, int j) {
    float s = 0.0f;
    #pragma unroll
    for (int d = 0; d < DDIM; d++) { float v = sp[j * DDIM + d]; s = fmaf(v, v, s); }
    return s;
}

// ---- block-wide "first bin with inclusive cum >= r" over NB bins ----
template<int NB, int BD>
__device__ void find_bin(const unsigned* hist, unsigned r, unsigned* warpsum,
                         unsigned* s_res, unsigned* s_prefix)
{
    const int tid = threadIdx.x;
    constexpr int PB = NB / BD;
    unsigned local[PB];
    unsigned v = 0;
    #pragma unroll
    for (int p = 0; p < PB; p++) { local[p] = hist[tid * PB + p]; v += local[p]; }

    unsigned inc = v;
    #pragma unroll
    for (int d = 1; d < 32; d <<= 1) {
        unsigned t = __shfl_up_sync(0xFFFFFFFFu, inc, d);
        if ((tid & 31) >= d) inc += t;
    }
    if ((tid & 31) == 31) warpsum[tid >> 5] = inc;
    if (tid == 0) *s_res = 0xFFFFFFFFu;
    __syncthreads();

    if (tid < 32) {
        constexpr int NW = BD / 32;
        unsigned w = (tid < NW) ? warpsum[tid] : 0u;
        #pragma unroll
        for (int d = 1; d < 32; d <<= 1) {
            unsigned t = __shfl_up_sync(0xFFFFFFFFu, w, d);
            if (tid >= d) w += t;
        }
        warpsum[tid] = w;
    }
    __syncthreads();

    unsigned base   = (tid >= 32) ? warpsum[(tid >> 5) - 1] : 0u;
    unsigned before = base + inc - v;
    unsigned run = before;
    unsigned myBin = 0xFFFFFFFFu;
    #pragma unroll
    for (int p = 0; p < PB; p++) {
        run += local[p];
        if (myBin == 0xFFFFFFFFu && run >= r) myBin = (unsigned)(tid * PB + p);
    }
    if (myBin != 0xFFFFFFFFu) atomicMin(s_res, myBin);
    __syncthreads();

    unsigned winner = *s_res;
    if (winner != 0xFFFFFFFFu && winner / PB == (unsigned)tid) {
        unsigned pf = before;
        for (unsigned p = 0; p < winner % PB; p++) pf += local[p];
        *s_prefix = pf;
    }
    __syncthreads();
}

// -------- kernel 1a: layers 0+1+2-slice (8 blocks) + zero scratch --------
__global__ __launch_bounds__(256) void mlpA_kernel(
    const float* __restrict__ x_in,
    const float* __restrict__ W0, const float* __restrict__ b0,
    const float* __restrict__ W1, const float* __restrict__ b1)
{
    __shared__ float x[DDIM];
    __shared__ float h0[256];
    __shared__ float part[256];
    int tid = threadIdx.x, b = blockIdx.x;

    {   // distributed scratch zero (8 blocks x 256 threads)
        int gt = b * 256 + tid;
        for (int i = gt; i < SLATE * NBINS; i += 8 * 256) { g_hist[i] = 0; g_hist2[i] = 0; }
        if (b == 0 && tid < 8) { g_candCount[tid] = 0; g_rdone[tid] = 0; }
        if (b == 0 && tid == 8) g_done = 0;
    }

    if (tid < DDIM) x[tid] = x_in[tid];
    __syncthreads();

    {   // layer 1: full 256 outputs per block (redundant; W0 is 20 KB)
        float acc = b0[tid];
        #pragma unroll
        for (int k = 0; k < DDIM; k++) acc = fmaf(x[k], W0[k * 256 + tid], acc);
        h0[tid] = leaky(acc);
    }
    __syncthreads();

    {   // layer 2 slice: outputs [64b, 64b+64); k split 4 ways
        int oo = tid & 63;
        int c  = tid >> 6;
        float acc = 0.0f;
        int k0 = c * 64;
        #pragma unroll 8
        for (int k = k0; k < k0 + 64; k++)
            acc = fmaf(h0[k], W1[k * 512 + 64 * b + oo], acc);
        part[tid] = acc;
    }
    __syncthreads();
    if (tid < 64) {
        float s = b1[64 * b + tid] + part[tid] + part[64 + tid]
                + part[128 + tid] + part[192 + tid];   // fixed order
        g_h1[64 * b + tid] = leaky(s);
    }
}

// -------- kernel 1b: layer 3 (4 blocks, 25 outputs each); PDL on mlpA ------
__global__ __launch_bounds__(256) void mlpB_kernel(
    const float* __restrict__ W2, const float* __restrict__ b2)
{
    __shared__ float h1s[512];
    __shared__ float part[256];
    int tid = threadIdx.x, b = blockIdx.x;

    cudaGridDependencySynchronize();                 // wait for mlpA (g_h1)
    h1s[tid] = g_h1[tid];
    h1s[256 + tid] = g_h1[256 + tid];
    __syncthreads();

    {   // outputs [25b, 25b+25); k split 8 ways
        int oo = tid & 31;
        int c  = tid >> 5;
        float acc = 0.0f;
        if (oo < 25) {
            int k0 = c * 64;
            #pragma unroll 8
            for (int k = k0; k < k0 + 64; k++)
                acc = fmaf(h1s[k], W2[k * 100 + 25 * b + oo], acc);
        }
        part[tid] = acc;
    }
    __syncthreads();
    if (tid < 25) {
        float s = b2[25 * b + tid];
        #pragma unroll
        for (int c = 0; c < 8; c++) s += part[c * 32 + tid];   // fixed order
        g_proto[25 * b + tid] = leaky(s);
    }
}

// -------- kernel 2: sample keys + coarse hist (1/64) + coarse-bin epilogue --
__global__ __launch_bounds__(512) void sample_kernel(const float* __restrict__ docs,
                                                     int N, int S)
{
    __shared__ unsigned shist[SLATE * NBINS];
    __shared__ __align__(16) float sp[100];
    __shared__ float    spn[SLATE];
    __shared__ unsigned swarp[32];
    __shared__ unsigned sres, spre, slast;
    int tid = threadIdx.x;

    for (int t = tid; t < SLATE * NBINS; t += 512) shist[t] = 0;   // pre-sync work
    cudaGridDependencySynchronize();                               // wait for mlpB
    if (tid < 100) sp[tid] = g_proto[tid];
    __syncthreads();
    if (tid < SLATE) spn[tid] = pn20(sp, tid);
    __syncthreads();

    const float4* d4 = (const float4*)docs;
    for (int s = blockIdx.x * blockDim.x + tid; s < S; s += gridDim.x * blockDim.x) {
        int i = ((s >> 8) << 14) + (s & 255);   // chunk c -> docs [16384c, 16384c+256)
        if (i >= N) {
            #pragma unroll
            for (int j = 0; j < SLATE; j++)
                g_skey[(size_t)j * SMAX + s] = 0xFFFFFFFFu;   // sentinel
            continue;
        }
        float4 dv[5];
        size_t base = (size_t)i * 5;
        #pragma unroll
        for (int q = 0; q < 5; q++) dv[q] = d4[base + q];
        float vv[20];
        unpack20(dv, vv);
        float cn2 = norm20(vv);
        #pragma unroll
        for (int j = 0; j < SLATE; j++) {
            float dot = dot20v((const float4*)&sp[j * DDIM], vv);
            unsigned key = key20(cn2, dot, spn[j]);
            g_skey[(size_t)j * SMAX + s] = key;
            unsigned hidx = j * NBINS + (key >> 21);
            unsigned am = __activemask();
            unsigned m  = __match_any_sync(am, hidx);
            if ((int)(threadIdx.x & 31) == (__ffs(m) - 1))
                atomicAdd(&shist[hidx], (unsigned)__popc(m));
        }
    }
    __syncthreads();
    for (int t = tid; t < SLATE * NBINS; t += 512) {
        unsigned c = shist[t];
        if (c) atomicAdd(&g_hist[t], c);
    }

    // ---- last-block ticket epilogue: per-row COARSE bin only (tiny) ----
    __threadfence();
    if (tid == 0) slast = (atomicAdd(&g_done, 1u) == gridDim.x - 1) ? 1u : 0u;
    __syncthreads();
    if (!slast) return;
    __threadfence();

    for (int r = 0; r < SLATE; r++) {
        for (int i = tid; i < NBINS; i += 512)
            shist[i] = __ldcg(&g_hist[r * NBINS + i]);
        __syncthreads();
        find_bin<NBINS, 512>(shist, STGT, swarp, &sres, &spre);
        if (tid == 0) { g_coarseBA[r] = sres; g_coarsePF[r] = spre; }
        __syncthreads();
    }
    if (tid == 0) g_done = 0;   // reset for graph replay
}

// -------- kernel 3: fine histogram + per-row ticket threshold; PDL ---------
// 5 rows x 16 chunk-blocks; coarse bin precomputed by sample's epilogue.
__global__ __launch_bounds__(512) void refineA_kernel(int S)
{
    __shared__ unsigned hist[NBINS];
    __shared__ unsigned swarp[32];
    __shared__ unsigned sres, spre, slast;
    int j = blockIdx.x / RCHUNK;          // row
    int c = blockIdx.x % RCHUNK;
    int tid = threadIdx.x;

    for (int i = tid; i < NBINS; i += 512) hist[i] = 0;   // pre-sync work
    cudaGridDependencySynchronize();                       // wait for sample
    unsigned bA  = g_coarseBA[j];
    unsigned pfA = g_coarsePF[j];
    __syncthreads();

    if (bA != 0xFFFFFFFFu) {
        int s0 = (int)(((long long)c * S) / RCHUNK);
        int s1 = (int)(((long long)(c + 1) * S) / RCHUNK);
        for (int s = s0 + tid; s < s1; s += 512) {
            unsigned k = g_skey[(size_t)j * SMAX + s];
            if ((k >> 21) == bA) atomicAdd(&hist[(k >> 10) & 0x7FFu], 1u);
        }
        __syncthreads();
        for (int i = tid; i < NBINS; i += 512) {
            unsigned v = hist[i];
            if (v) atomicAdd(&g_hist2[j * NBINS + i], v);
        }
    }

    // per-row ticket: last of the 16 chunk-blocks computes the threshold
    __threadfence();
    if (tid == 0) slast = (atomicAdd(&g_rdone[j], 1u) == RCHUNK - 1) ? 1u : 0u;
    __syncthreads();
    if (!slast) return;
    __threadfence();

    if (bA == 0xFFFFFFFFu) {
        if (tid == 0) { g_thresh[j] = 0xFFFFFFFFu; g_rdone[j] = 0; }
        return;
    }
    unsigned rB = STGT - pfA;
    for (int i = tid; i < NBINS; i += 512) hist[i] = __ldcg(&g_hist2[j * NBINS + i]);
    __syncthreads();
    find_bin<NBINS, 512>(hist, rB, swarp, &sres, &spre);
    if (tid == 0) {
        unsigned long long T =
            ((((unsigned long long)bA << 11) | sres) + 1ull) << 10;
        g_thresh[j] = (T > 0xFFFFFFFFull) ? 0xFFFFFFFFu : (unsigned)T;
        g_rdone[j] = 0;               // reset for graph replay
    }
}

// -------- kernel 4: fused score+collect, direct streaming LDG; PDL ---------
__global__ __launch_bounds__(512) void score_kernel(const float* __restrict__ docs, int N)
{
    __shared__ __align__(16) float sp[100];
    __shared__ float    spn[SLATE];
    __shared__ unsigned sT[SLATE];
    int tid = threadIdx.x;

    cudaGridDependencySynchronize();                 // wait for refineA
    if (tid < 100) sp[tid] = g_proto[tid];
    __syncthreads();
    if (tid < SLATE) { spn[tid] = pn20(sp, tid); sT[tid] = g_thresh[tid]; }
    __syncthreads();

    const int lane = tid & 31;
    const float4* d4 = (const float4*)docs;
    int stride = gridDim.x * blockDim.x;

    for (int i = blockIdx.x * blockDim.x + tid; i < N; i += stride) {
        const float4* dp = d4 + (size_t)i * 5;
        float4 dv[5];
        #pragma unroll
        for (int q = 0; q < 5; q++) dv[q] = __ldcs(dp + q);
        float vv[20];
        unpack20(dv, vv);
        float cn2 = norm20(vv);

        unsigned keys[SLATE];
        unsigned hit = 0;
        #pragma unroll
        for (int j = 0; j < SLATE; j++) {
            float dot = dot20v((const float4*)&sp[j * DDIM], vv);
            keys[j] = key20(cn2, dot, spn[j]);
            hit |= (keys[j] < sT[j]) ? (1u << j) : 0u;
        }

        unsigned am = __activemask();
        if (__ballot_sync(am, hit != 0)) {      // rare slow path
            #pragma unroll
            for (int j = 0; j < SLATE; j++) {
                bool h = (hit >> j) & 1u;
                unsigned m = __ballot_sync(am, h);
                if (m) {
                    int ldr = __ffs(m) - 1;
                    unsigned bpos = 0;
                    if (lane == ldr)
                        bpos = atomicAdd(&g_candCount[j], (unsigned)__popc(m));
                    bpos = __shfl_sync(am, bpos, ldr);
                    if (h) {
                        unsigned pos = bpos + (unsigned)__popc(m & ((1u << lane) - 1u));
                        if (pos < CAP)
                            g_cand[(size_t)j * CAP + pos] =
                                ((unsigned long long)keys[j] << 32) | (unsigned)i;
                    }
                }
            }
        }
    }
}

// -------- kernel 5: radix select of exact 100th + rank survivors + gather ----
__global__ __launch_bounds__(1024) void select_kernel(
    const float* __restrict__ docs, float* __restrict__ out, int out_size)
{
    extern __shared__ unsigned long long sc[];
    __shared__ unsigned           hist[NBINS];
    __shared__ unsigned           swarp[32];
    __shared__ unsigned           sres, spre;
    __shared__ unsigned long long sv[SV_CAP];
    __shared__ unsigned           svCount;

    int j   = blockIdx.x;
    int tid = threadIdx.x;
    size_t cbase = (size_t)j * CAP;

    if (tid == 0) svCount = 0;
    for (int i = tid; i < NBINS; i += 1024) hist[i] = 0;   // pre-sync work
    cudaGridDependencySynchronize();                       // wait for score
    int n = (int)min(g_candCount[j], (unsigned)CAP);
    int nsh = n < SH_CAND ? n : SH_CAND;

    for (int t = tid; t < nsh; t += 1024) sc[t] = g_cand[cbase + t];
    __syncthreads();

    // pass A: bits 31..21
    for (int t = tid; t < n; t += 1024) {
        unsigned k = (unsigned)(((t < nsh) ? sc[t] : g_cand[cbase + t]) >> 32);
        unsigned b = k >> 21;
        unsigned am = __activemask();
        unsigned m  = __match_any_sync(am, b);
        if ((int)(tid & 31) == (__ffs(m) - 1)) atomicAdd(&hist[b], (unsigned)__popc(m));
    }
    __syncthreads();
    find_bin<NBINS, 1024>(hist, KSEL, swarp, &sres, &spre);
    unsigned bA = sres;
    unsigned rB = KSEL - spre;
    __syncthreads();

    // pass B: bits 20..10 within bA
    for (int i = tid; i < NBINS; i += 1024) hist[i] = 0;
    __syncthreads();
    for (int t = tid; t < n; t += 1024) {
        unsigned k = (unsigned)(((t < nsh) ? sc[t] : g_cand[cbase + t]) >> 32);
        if ((k >> 21) == bA) atomicAdd(&hist[(k >> 10) & 0x7FFu], 1u);
    }
    __syncthreads();
    find_bin<NBINS, 1024>(hist, rB, swarp, &sres, &spre);
    unsigned bB = sres;
    unsigned rC = rB - spre;
    unsigned hi21 = (bA << 11) | bB;
    __syncthreads();

    // pass C: bits 9..0 within (bA,bB)
    if (tid < 1024) hist[tid] = 0;
    __syncthreads();
    for (int t = tid; t < n; t += 1024) {
        unsigned k = (unsigned)(((t < nsh) ? sc[t] : g_cand[cbase + t]) >> 32);
        if ((k >> 10) == hi21) atomicAdd(&hist[k & 0x3FFu], 1u);
    }
    __syncthreads();
    find_bin<1024, 1024>(hist, rC, swarp, &sres, &spre);
    unsigned Kstar = (hi21 << 10) | sres;
    __syncthreads();

    // survivors: key <= Kstar (ties resolved by packed 64-bit rank)
    for (int t = tid; t < n; t += 1024) {
        unsigned long long pk = (t < nsh) ? sc[t] : g_cand[cbase + t];
        if ((unsigned)(pk >> 32) <= Kstar) {
            unsigned pos = atomicAdd(&svCount, 1u);
            if (pos < SV_CAP) sv[pos] = pk;
        }
    }
    __syncthreads();

    int S = (int)min(svCount, (unsigned)SV_CAP);
    for (int t = tid; t < S; t += 1024) {
        unsigned long long my = sv[t];
        int rank = 0;
        for (int s = 0; s < S; s++) rank += (sv[s] < my);
        if (rank < KSEL) {
            unsigned di = (unsigned)(my & 0xFFFFFFFFu);
            int orow = j * KSEL + rank;
            if (out_size >= SLATE * KSEL * DDIM) {
                const float4* s4 = (const float4*)(docs + (size_t)di * DDIM);
                float4* o4 = (float4*)(out + (size_t)orow * DDIM);
                #pragma unroll
                for (int q = 0; q < 5; q++) o4[q] = s4[q];
                if (out_size >= SLATE * KSEL * DDIM + SLATE * KSEL)
                    out[SLATE * KSEL * DDIM + orow] = (float)di;
            } else {
                out[orow] = (float)di;
            }
        }
    }
}

extern "C" void kernel_launch(void* const* d_in, const int* in_sizes, int n_in,
                              void* d_out, int out_size)
{
    const float* state = (const float*)d_in[0];
    const float* docs  = (const float*)d_in[1];
    const float* W0    = (const float*)d_in[2];
    const float* b0    = (const float*)d_in[3];
    const float* W1    = (const float*)d_in[4];
    const float* b1    = (const float*)d_in[5];
    const float* W2    = (const float*)d_in[6];
    const float* b2    = (const float*)d_in[7];
    float* out = (float*)d_out;

    int N = in_sizes[1] / DDIM;
    int S = N >> 6;               // 1/64 sample
    if (S < 1) S = N;
    if (S > SMAX) S = SMAX;

    static int inited = 0;
    if (!inited) {
        cudaFuncSetAttribute(select_kernel,
            cudaFuncAttributeMaxDynamicSharedMemorySize, SH_CAND * sizeof(unsigned long long));
        inited = 1;
    }

    int sblocks = (N + 512 * 2 - 1) / (512 * 2);
    if (sblocks > 1184) sblocks = 1184;      // 8 blocks/SM
    if (sblocks < 1) sblocks = 1;

    // PDL: downstream kernels launch early, block in
    // cudaGridDependencySynchronize() until the upstream grid completes.
    cudaLaunchAttribute pdl[1];
    pdl[0].id = cudaLaunchAttributeProgrammaticStreamSerialization;
    pdl[0].val.programmaticStreamSerializationAllowed = 1;

    mlpA_kernel<<<8, 256>>>(state, W0, b0, W1, b1);

    {
        cudaLaunchConfig_t cfg = {};
        cfg.gridDim = dim3(4); cfg.blockDim = dim3(256);
        cfg.attrs = pdl; cfg.numAttrs = 1;
        cudaLaunchKernelEx(&cfg, mlpB_kernel, W2, b2);
    }
    {
        cudaLaunchConfig_t cfg = {};
        cfg.gridDim = dim3(128); cfg.blockDim = dim3(512);
        cfg.attrs = pdl; cfg.numAttrs = 1;
        cudaLaunchKernelEx(&cfg, sample_kernel, docs, N, S);
    }
    {
        cudaLaunchConfig_t cfg = {};
        cfg.gridDim = dim3(SLATE * RCHUNK); cfg.blockDim = dim3(512);
        cfg.attrs = pdl; cfg.numAttrs = 1;
        cudaLaunchKernelEx(&cfg, refineA_kernel, S);
    }
    {
        cudaLaunchConfig_t cfg = {};
        cfg.gridDim = dim3(sblocks); cfg.blockDim = dim3(512);
        cfg.attrs = pdl; cfg.numAttrs = 1;
        cudaLaunchKernelEx(&cfg, score_kernel, docs, N);
    }
    {
        cudaLaunchConfig_t cfg = {};
        cfg.gridDim = dim3(SLATE); cfg.blockDim = dim3(1024);
        cfg.dynamicSmemBytes = SH_CAND * sizeof(unsigned long long);
        cfg.attrs = pdl; cfg.numAttrs = 1;
        cudaLaunchKernelEx(&cfg, select_kernel, docs, out, out_size);
    }
}

// round 17
// speedup vs baseline: 1.2799x; 1.2799x over previous
#include <cuda_runtime.h>
#include <cstdint>

#define SLATE   5
#define DDIM    20
#define KSEL    100
#define NBINS   2048
#define CAP     131072
#define SMAX    131072
#define SH_CAND 12288
#define SV_CAP  512
#define STGT    128        // sample-count guarantee target (>= KSEL)
#define RCHUNK  16         // refineA chunks per row

// -------- device scratch (allocation-free module globals) --------
__device__ float              g_h1[512];
__device__ float              g_proto[128];
__device__ unsigned           g_hist[SLATE * NBINS];
__device__ unsigned           g_hist2[SLATE * NBINS];
__device__ unsigned           g_skey[(size_t)SLATE * SMAX];   // sample keys
__device__ unsigned           g_thresh[8];                    // exclusive key limit
__device__ unsigned           g_candCount[8];
__device__ unsigned long long g_cand[(size_t)SLATE * CAP];
__device__ unsigned           g_rdone[8];                     // per-row tickets

__device__ __forceinline__ float leaky(float x) { return x > 0.0f ? x : 0.01f * x; }

// ---- scalar math: sample AND score use identical sequences (bit-identical keys)
__device__ __forceinline__ void unpack20(const float4* d5, float* vv) {
    #pragma unroll
    for (int q = 0; q < 5; q++) {
        float4 v = d5[q];
        vv[4*q+0] = v.x; vv[4*q+1] = v.y; vv[4*q+2] = v.z; vv[4*q+3] = v.w;
    }
}
__device__ __forceinline__ float norm20(const float* vv) {
    float c = 0.0f;
    #pragma unroll
    for (int k = 0; k < DDIM; k++) c = fmaf(vv[k], vv[k], c);
    return c;
}
__device__ __forceinline__ float dot20v(const float4* p, const float* vv) {
    float d = 0.0f;
    #pragma unroll
    for (int q = 0; q < 5; q++) {
        float4 w = p[q];
        d = fmaf(w.x, vv[4*q+0], d); d = fmaf(w.y, vv[4*q+1], d);
        d = fmaf(w.z, vv[4*q+2], d); d = fmaf(w.w, vv[4*q+3], d);
    }
    return d;
}
__device__ __forceinline__ unsigned key20(float cn2, float dot, float pn) {
    float d2 = fmaf(-2.0f, dot, cn2) + pn;
    d2 = fmaxf(d2, 0.0f);               // positive floats: raw bits monotone
    return __float_as_uint(d2);
}
// spn from shared proto — IDENTICAL fmaf order in sample and score => same bits
__device__ __forceinline__ float pn20(const float* sp, int j) {
    float s = 0.0f;
    #pragma unroll
    for (int d = 0; d < DDIM; d++) { float v = sp[j * DDIM + d]; s = fmaf(v, v, s); }
    return s;
}

// ---- block-wide "first bin with inclusive cum >= r" over NB bins ----
template<int NB, int BD>
__device__ void find_bin(const unsigned* hist, unsigned r, unsigned* warpsum,
                         unsigned* s_res, unsigned* s_prefix)
{
    const int tid = threadIdx.x;
    constexpr int PB = NB / BD;
    unsigned local[PB];
    unsigned v = 0;
    #pragma unroll
    for (int p = 0; p < PB; p++) { local[p] = hist[tid * PB + p]; v += local[p]; }

    unsigned inc = v;
    #pragma unroll
    for (int d = 1; d < 32; d <<= 1) {
        unsigned t = __shfl_up_sync(0xFFFFFFFFu, inc, d);
        if ((tid & 31) >= d) inc += t;
    }
    if ((tid & 31) == 31) warpsum[tid >> 5] = inc;
    if (tid == 0) *s_res = 0xFFFFFFFFu;
    __syncthreads();

    if (tid < 32) {
        constexpr int NW = BD / 32;
        unsigned w = (tid < NW) ? warpsum[tid] : 0u;
        #pragma unroll
        for (int d = 1; d < 32; d <<= 1) {
            unsigned t = __shfl_up_sync(0xFFFFFFFFu, w, d);
            if (tid >= d) w += t;
        }
        warpsum[tid] = w;
    }
    __syncthreads();

    unsigned base   = (tid >= 32) ? warpsum[(tid >> 5) - 1] : 0u;
    unsigned before = base + inc - v;
    unsigned run = before;
    unsigned myBin = 0xFFFFFFFFu;
    #pragma unroll
    for (int p = 0; p < PB; p++) {
        run += local[p];
        if (myBin == 0xFFFFFFFFu && run >= r) myBin = (unsigned)(tid * PB + p);
    }
    if (myBin != 0xFFFFFFFFu) atomicMin(s_res, myBin);
    __syncthreads();

    unsigned winner = *s_res;
    if (winner != 0xFFFFFFFFu && winner / PB == (unsigned)tid) {
        unsigned pf = before;
        for (unsigned p = 0; p < winner % PB; p++) pf += local[p];
        *s_prefix = pf;
    }
    __syncthreads();
}

// -------- kernel 1a: layers 0+1+2-slice (8 blocks) + zero scratch --------
__global__ __launch_bounds__(256) void mlpA_kernel(
    const float* __restrict__ x_in,
    const float* __restrict__ W0, const float* __restrict__ b0,
    const float* __restrict__ W1, const float* __restrict__ b1)
{
    __shared__ float x[DDIM];
    __shared__ float h0[256];
    __shared__ float part[256];
    int tid = threadIdx.x, b = blockIdx.x;

    {   // distributed scratch zero (8 blocks x 256 threads)
        int gt = b * 256 + tid;
        for (int i = gt; i < SLATE * NBINS; i += 8 * 256) { g_hist[i] = 0; g_hist2[i] = 0; }
        if (b == 0 && tid < 8) { g_candCount[tid] = 0; g_rdone[tid] = 0; }
    }

    if (tid < DDIM) x[tid] = x_in[tid];
    __syncthreads();

    {   // layer 1: full 256 outputs per block (redundant; W0 is 20 KB)
        float acc = b0[tid];
        #pragma unroll
        for (int k = 0; k < DDIM; k++) acc = fmaf(x[k], W0[k * 256 + tid], acc);
        h0[tid] = leaky(acc);
    }
    __syncthreads();

    {   // layer 2 slice: outputs [64b, 64b+64); k split 4 ways
        int oo = tid & 63;
        int c  = tid >> 6;
        float acc = 0.0f;
        int k0 = c * 64;
        #pragma unroll 8
        for (int k = k0; k < k0 + 64; k++)
            acc = fmaf(h0[k], W1[k * 512 + 64 * b + oo], acc);
        part[tid] = acc;
    }
    __syncthreads();
    if (tid < 64) {
        float s = b1[64 * b + tid] + part[tid] + part[64 + tid]
                + part[128 + tid] + part[192 + tid];   // fixed order
        g_h1[64 * b + tid] = leaky(s);
    }
}

// -------- kernel 1b: layer 3 (4 blocks, 25 outputs each); PDL on mlpA ------
__global__ __launch_bounds__(256) void mlpB_kernel(
    const float* __restrict__ W2, const float* __restrict__ b2)
{
    __shared__ float h1s[512];
    __shared__ float part[256];
    int tid = threadIdx.x, b = blockIdx.x;

    cudaGridDependencySynchronize();                 // wait for mlpA (g_h1)
    h1s[tid] = g_h1[tid];
    h1s[256 + tid] = g_h1[256 + tid];
    __syncthreads();

    {   // outputs [25b, 25b+25); k split 8 ways
        int oo = tid & 31;
        int c  = tid >> 5;
        float acc = 0.0f;
        if (oo < 25) {
            int k0 = c * 64;
            #pragma unroll 8
            for (int k = k0; k < k0 + 64; k++)
                acc = fmaf(h1s[k], W2[k * 100 + 25 * b + oo], acc);
        }
        part[tid] = acc;
    }
    __syncthreads();
    if (tid < 25) {
        float s = b2[25 * b + tid];
        #pragma unroll
        for (int c = 0; c < 8; c++) s += part[c * 32 + tid];   // fixed order
        g_proto[25 * b + tid] = leaky(s);
    }
}

// -------- kernel 2: sample keys + coarse histogram (1/32 of docs); PDL -----
__global__ __launch_bounds__(512) void sample_kernel(const float* __restrict__ docs,
                                                     int N, int S)
{
    __shared__ unsigned shist[SLATE * NBINS];
    __shared__ __align__(16) float sp[100];
    __shared__ float    spn[SLATE];
    int tid = threadIdx.x;

    for (int t = tid; t < SLATE * NBINS; t += 512) shist[t] = 0;   // pre-sync work
    cudaGridDependencySynchronize();                               // wait for mlpB
    if (tid < 100) sp[tid] = g_proto[tid];
    __syncthreads();
    if (tid < SLATE) spn[tid] = pn20(sp, tid);
    __syncthreads();

    const float4* d4 = (const float4*)docs;
    for (int s = blockIdx.x * blockDim.x + tid; s < S; s += gridDim.x * blockDim.x) {
        int i = ((s >> 8) << 13) + (s & 255);   // chunk c -> docs [8192c, 8192c+256)
        if (i >= N) {
            #pragma unroll
            for (int j = 0; j < SLATE; j++)
                g_skey[(size_t)j * SMAX + s] = 0xFFFFFFFFu;   // sentinel
            continue;
        }
        float4 dv[5];
        size_t base = (size_t)i * 5;
        #pragma unroll
        for (int q = 0; q < 5; q++) dv[q] = d4[base + q];
        float vv[20];
        unpack20(dv, vv);
        float cn2 = norm20(vv);
        #pragma unroll
        for (int j = 0; j < SLATE; j++) {
            float dot = dot20v((const float4*)&sp[j * DDIM], vv);
            unsigned key = key20(cn2, dot, spn[j]);
            g_skey[(size_t)j * SMAX + s] = key;
            unsigned hidx = j * NBINS + (key >> 21);
            unsigned am = __activemask();
            unsigned m  = __match_any_sync(am, hidx);
            if ((int)(threadIdx.x & 31) == (__ffs(m) - 1))
                atomicAdd(&shist[hidx], (unsigned)__popc(m));
        }
    }
    __syncthreads();
    for (int t = tid; t < SLATE * NBINS; t += 512) {
        unsigned c = shist[t];
        if (c) atomicAdd(&g_hist[t], c);
    }
}

// -------- kernel 3: fine histogram + per-row ticket threshold; PDL ---------
// 5 rows x 16 chunk-blocks; each block recomputes its row's coarse bin.
__global__ __launch_bounds__(512) void refineA_kernel(int S)
{
    __shared__ unsigned hist[NBINS];
    __shared__ unsigned swarp[32];
    __shared__ unsigned sres, spre, slast;
    int j = blockIdx.x / RCHUNK;          // row
    int c = blockIdx.x % RCHUNK;
    int tid = threadIdx.x;

    cudaGridDependencySynchronize();                 // wait for sample
    for (int i = tid; i < NBINS; i += 512) hist[i] = g_hist[j * NBINS + i];
    __syncthreads();
    find_bin<NBINS, 512>(hist, STGT, swarp, &sres, &spre);
    unsigned bA = sres, pfA = spre;
    __syncthreads();

    if (bA != 0xFFFFFFFFu) {
        for (int i = tid; i < NBINS; i += 512) hist[i] = 0;
        __syncthreads();
        int s0 = (int)(((long long)c * S) / RCHUNK);
        int s1 = (int)(((long long)(c + 1) * S) / RCHUNK);
        for (int s = s0 + tid; s < s1; s += 512) {
            unsigned k = g_skey[(size_t)j * SMAX + s];
            if ((k >> 21) == bA) atomicAdd(&hist[(k >> 10) & 0x7FFu], 1u);
        }
        __syncthreads();
        for (int i = tid; i < NBINS; i += 512) {
            unsigned v = hist[i];
            if (v) atomicAdd(&g_hist2[j * NBINS + i], v);
        }
    }

    // per-row ticket: last of the 16 chunk-blocks computes the threshold
    __threadfence();
    if (tid == 0) slast = (atomicAdd(&g_rdone[j], 1u) == RCHUNK - 1) ? 1u : 0u;
    __syncthreads();
    if (!slast) return;
    __threadfence();

    if (bA == 0xFFFFFFFFu) {
        if (tid == 0) { g_thresh[j] = 0xFFFFFFFFu; g_rdone[j] = 0; }
        return;
    }
    unsigned rB = STGT - pfA;
    for (int i = tid; i < NBINS; i += 512) hist[i] = __ldcg(&g_hist2[j * NBINS + i]);
    __syncthreads();
    find_bin<NBINS, 512>(hist, rB, swarp, &sres, &spre);
    if (tid == 0) {
        unsigned long long T =
            ((((unsigned long long)bA << 11) | sres) + 1ull) << 10;
        g_thresh[j] = (T > 0xFFFFFFFFull) ? 0xFFFFFFFFu : (unsigned)T;
        g_rdone[j] = 0;               // reset for graph replay
    }
}

// -------- kernel 4: fused score+collect, direct streaming LDG; PDL ---------
__global__ __launch_bounds__(512) void score_kernel(const float* __restrict__ docs, int N)
{
    __shared__ __align__(16) float sp[100];
    __shared__ float    spn[SLATE];
    __shared__ unsigned sT[SLATE];
    int tid = threadIdx.x;

    cudaGridDependencySynchronize();                 // wait for refineA
    if (tid < 100) sp[tid] = g_proto[tid];
    __syncthreads();
    if (tid < SLATE) { spn[tid] = pn20(sp, tid); sT[tid] = g_thresh[tid]; }
    __syncthreads();

    const int lane = tid & 31;
    const float4* d4 = (const float4*)docs;
    int stride = gridDim.x * blockDim.x;

    for (int i = blockIdx.x * blockDim.x + tid; i < N; i += stride) {
        const float4* dp = d4 + (size_t)i * 5;
        float4 dv[5];
        #pragma unroll
        for (int q = 0; q < 5; q++) dv[q] = __ldcs(dp + q);
        float vv[20];
        unpack20(dv, vv);
        float cn2 = norm20(vv);

        unsigned keys[SLATE];
        unsigned hit = 0;
        #pragma unroll
        for (int j = 0; j < SLATE; j++) {
            float dot = dot20v((const float4*)&sp[j * DDIM], vv);
            keys[j] = key20(cn2, dot, spn[j]);
            hit |= (keys[j] < sT[j]) ? (1u << j) : 0u;
        }

        unsigned am = __activemask();
        if (__ballot_sync(am, hit != 0)) {      // rare slow path
            #pragma unroll
            for (int j = 0; j < SLATE; j++) {
                bool h = (hit >> j) & 1u;
                unsigned m = __ballot_sync(am, h);
                if (m) {
                    int ldr = __ffs(m) - 1;
                    unsigned bpos = 0;
                    if (lane == ldr)
                        bpos = atomicAdd(&g_candCount[j], (unsigned)__popc(m));
                    bpos = __shfl_sync(am, bpos, ldr);
                    if (h) {
                        unsigned pos = bpos + (unsigned)__popc(m & ((1u << lane) - 1u));
                        if (pos < CAP)
                            g_cand[(size_t)j * CAP + pos] =
                                ((unsigned long long)keys[j] << 32) | (unsigned)i;
                    }
                }
            }
        }
    }
}

// -------- kernel 5: radix select of exact 100th + rank survivors + gather ----
__global__ __launch_bounds__(1024) void select_kernel(
    const float* __restrict__ docs, float* __restrict__ out, int out_size)
{
    extern __shared__ unsigned long long sc[];
    __shared__ unsigned           hist[NBINS];
    __shared__ unsigned           swarp[32];
    __shared__ unsigned           sres, spre;
    __shared__ unsigned long long sv[SV_CAP];
    __shared__ unsigned           svCount;

    int j   = blockIdx.x;
    int tid = threadIdx.x;
    size_t cbase = (size_t)j * CAP;

    if (tid == 0) svCount = 0;
    for (int i = tid; i < NBINS; i += 1024) hist[i] = 0;   // pre-sync work
    cudaGridDependencySynchronize();                       // wait for score
    int n = (int)min(g_candCount[j], (unsigned)CAP);
    int nsh = n < SH_CAND ? n : SH_CAND;

    for (int t = tid; t < nsh; t += 1024) sc[t] = g_cand[cbase + t];
    __syncthreads();

    // pass A: bits 31..21
    for (int t = tid; t < n; t += 1024) {
        unsigned k = (unsigned)(((t < nsh) ? sc[t] : g_cand[cbase + t]) >> 32);
        unsigned b = k >> 21;
        unsigned am = __activemask();
        unsigned m  = __match_any_sync(am, b);
        if ((int)(tid & 31) == (__ffs(m) - 1)) atomicAdd(&hist[b], (unsigned)__popc(m));
    }
    __syncthreads();
    find_bin<NBINS, 1024>(hist, KSEL, swarp, &sres, &spre);
    unsigned bA = sres;
    unsigned rB = KSEL - spre;
    __syncthreads();

    // pass B: bits 20..10 within bA
    for (int i = tid; i < NBINS; i += 1024) hist[i] = 0;
    __syncthreads();
    for (int t = tid; t < n; t += 1024) {
        unsigned k = (unsigned)(((t < nsh) ? sc[t] : g_cand[cbase + t]) >> 32);
        if ((k >> 21) == bA) atomicAdd(&hist[(k >> 10) & 0x7FFu], 1u);
    }
    __syncthreads();
    find_bin<NBINS, 1024>(hist, rB, swarp, &sres, &spre);
    unsigned bB = sres;
    unsigned rC = rB - spre;
    unsigned hi21 = (bA << 11) | bB;
    __syncthreads();

    // pass C: bits 9..0 within (bA,bB)
    if (tid < 1024) hist[tid] = 0;
    __syncthreads();
    for (int t = tid; t < n; t += 1024) {
        unsigned k = (unsigned)(((t < nsh) ? sc[t] : g_cand[cbase + t]) >> 32);
        if ((k >> 10) == hi21) atomicAdd(&hist[k & 0x3FFu], 1u);
    }
    __syncthreads();
    find_bin<1024, 1024>(hist, rC, swarp, &sres, &spre);
    unsigned Kstar = (hi21 << 10) | sres;
    __syncthreads();

    // survivors: key <= Kstar (ties resolved by packed 64-bit rank)
    for (int t = tid; t < n; t += 1024) {
        unsigned long long pk = (t < nsh) ? sc[t] : g_cand[cbase + t];
        if ((unsigned)(pk >> 32) <= Kstar) {
            unsigned pos = atomicAdd(&svCount, 1u);
            if (pos < SV_CAP) sv[pos] = pk;
        }
    }
    __syncthreads();

    int S = (int)min(svCount, (unsigned)SV_CAP);
    for (int t = tid; t < S; t += 1024) {
        unsigned long long my = sv[t];
        int rank = 0;
        for (int s = 0; s < S; s++) rank += (sv[s] < my);
        if (rank < KSEL) {
            unsigned di = (unsigned)(my & 0xFFFFFFFFu);
            int orow = j * KSEL + rank;
            if (out_size >= SLATE * KSEL * DDIM) {
                const float4* s4 = (const float4*)(docs + (size_t)di * DDIM);
                float4* o4 = (float4*)(out + (size_t)orow * DDIM);
                #pragma unroll
                for (int q = 0; q < 5; q++) o4[q] = s4[q];
                if (out_size >= SLATE * KSEL * DDIM + SLATE * KSEL)
                    out[SLATE * KSEL * DDIM + orow] = (float)di;
            } else {
                out[orow] = (float)di;
            }
        }
    }
}

extern "C" void kernel_launch(void* const* d_in, const int* in_sizes, int n_in,
                              void* d_out, int out_size)
{
    const float* state = (const float*)d_in[0];
    const float* docs  = (const float*)d_in[1];
    const float* W0    = (const float*)d_in[2];
    const float* b0    = (const float*)d_in[3];
    const float* W1    = (const float*)d_in[4];
    const float* b1    = (const float*)d_in[5];
    const float* W2    = (const float*)d_in[6];
    const float* b2    = (const float*)d_in[7];
    float* out = (float*)d_out;

    int N = in_sizes[1] / DDIM;
    int S = N >> 5;               // 1/32 sample
    if (S < 1) S = N;
    if (S > SMAX) S = SMAX;

    static int inited = 0;
    if (!inited) {
        cudaFuncSetAttribute(select_kernel,
            cudaFuncAttributeMaxDynamicSharedMemorySize, SH_CAND * sizeof(unsigned long long));
        inited = 1;
    }

    int sblocks = (N + 512 * 2 - 1) / (512 * 2);
    if (sblocks > 1184) sblocks = 1184;      // 8 blocks/SM
    if (sblocks < 1) sblocks = 1;

    // PDL: downstream kernels launch early, block in
    // cudaGridDependencySynchronize() until the upstream grid completes.
    cudaLaunchAttribute pdl[1];
    pdl[0].id = cudaLaunchAttributeProgrammaticStreamSerialization;
    pdl[0].val.programmaticStreamSerializationAllowed = 1;

    mlpA_kernel<<<8, 256>>>(state, W0, b0, W1, b1);

    {
        cudaLaunchConfig_t cfg = {};
        cfg.gridDim = dim3(4); cfg.blockDim = dim3(256);
        cfg.attrs = pdl; cfg.numAttrs = 1;
        cudaLaunchKernelEx(&cfg, mlpB_kernel, W2, b2);
    }
    {
        cudaLaunchConfig_t cfg = {};
        cfg.gridDim = dim3(128); cfg.blockDim = dim3(512);
        cfg.attrs = pdl; cfg.numAttrs = 1;
        cudaLaunchKernelEx(&cfg, sample_kernel, docs, N, S);
    }
    {
        cudaLaunchConfig_t cfg = {};
        cfg.gridDim = dim3(SLATE * RCHUNK); cfg.blockDim = dim3(512);
        cfg.attrs = pdl; cfg.numAttrs = 1;
        cudaLaunchKernelEx(&cfg, refineA_kernel, S);
    }
    {
        cudaLaunchConfig_t cfg = {};
        cfg.gridDim = dim3(sblocks); cfg.blockDim = dim3(512);
        cfg.attrs = pdl; cfg.numAttrs = 1;
        cudaLaunchKernelEx(&cfg, score_kernel, docs, N);
    }
    {
        cudaLaunchConfig_t cfg = {};
        cfg.gridDim = dim3(SLATE); cfg.blockDim = dim3(1024);
        cfg.dynamicSmemBytes = SH_CAND * sizeof(unsigned long long);
        cfg.attrs = pdl; cfg.numAttrs = 1;
        cudaLaunchKernelEx(&cfg, select_kernel, docs, out, out_size);
    }
}